// round 9
// baseline (speedup 1.0000x reference)
#include <cuda_runtime.h>
#include <cuda_fp16.h>
#include <cstdint>

#define N_NODES 100000
#define N_EDGES 1600000
#define D 128
#define CAP 64            // bin capacity per destination
#define GM 128            // nodes per CTA

// smem chunk buffer: 128 rows x 64 halves, XOR-swizzled, 16 KB
#define CHB (128 * 64)

// ---- scratch (no allocations allowed) ----
__device__ __half g_msgh[N_NODES * D];     // fallback-only deposit area
__device__ int    g_cnt[N_NODES];
__device__ int    g_bin[N_NODES * CAP];
__device__ __half g_wth[128 * 256];        // [Wl|Wr] fp16, [n][k]
__device__ __half g_xh[N_NODES * D];       // fp16 copy of x
__device__ int    g_is64;

__device__ __forceinline__ void mma_f16(float* c, const uint32_t* a,
                                        uint32_t b0, uint32_t b1) {
    asm volatile(
        "mma.sync.aligned.m16n8k16.row.col.f32.f16.f16.f32 "
        "{%0,%1,%2,%3}, {%4,%5,%6,%7}, {%8,%9}, {%0,%1,%2,%3};"
        : "+f"(c[0]), "+f"(c[1]), "+f"(c[2]), "+f"(c[3])
        : "r"(a[0]), "r"(a[1]), "r"(a[2]), "r"(a[3]), "r"(b0), "r"(b1));
}
__device__ __forceinline__ uint32_t smem_u32(const void* p) {
    uint32_t a;
    asm("{ .reg .u64 t; cvta.to.shared.u64 t, %1; cvt.u32.u64 %0, t; }" : "=r"(a) : "l"(p));
    return a;
}
__device__ __forceinline__ void cpa16(uint32_t dst, const void* src) {
    asm volatile("cp.async.cg.shared.global [%0], [%1], 16;" :: "r"(dst), "l"(src));
}
#define CP_COMMIT() asm volatile("cp.async.commit_group;" ::: "memory")
#define CP_WAIT(n)  asm volatile("cp.async.wait_group %0;" :: "n"(n) : "memory")

// byte offset of (row, kb) in a swizzled 128x128B chunk buffer; kb = byte in row
__device__ __forceinline__ int swz(int row, int kb) {
    return row * 128 + (kb ^ ((row & 7) << 4));
}

// ============ prep: dtype detect + W->fp16 + cnt zero + x->fp16 =======
__global__ void prep_kernel(const float* __restrict__ Wl,
                            const float* __restrict__ Wr,
                            const float* __restrict__ x,
                            const long long* __restrict__ ei64,
                            __half2* __restrict__ wth2,
                            int* __restrict__ cnt,
                            __half2* __restrict__ xh2) {
    if (blockIdx.x == 0 && threadIdx.x < 32) {
        int lane = threadIdx.x;
        int bad = 0;
        for (int i = lane; i < 1024; i += 32) {
            long long v = ei64[i];
            if (v < 0 || v >= N_NODES) bad = 1;
        }
        unsigned m = __ballot_sync(0xFFFFFFFFu, bad);
        if (lane == 0) g_is64 = (m == 0u) ? 1 : 0;
    }
    int i = blockIdx.x * 256 + threadIdx.x;
    if (i < 128 * 128) {
        int n = i >> 7, k = (i & 127) * 2;
        float a, b;
        if (k < 128) { a = Wl[n * 128 + k];       b = Wl[n * 128 + k + 1]; }
        else         { a = Wr[n * 128 + k - 128]; b = Wr[n * 128 + k - 127]; }
        wth2[i] = __floats2half2_rn(a, b);
    }
    if (i < N_NODES) cnt[i] = 0;
    if (i < N_NODES * D / 2) {
        float2 v = ((const float2*)x)[i];
        xh2[i] = __floats2half2_rn(v.x, v.y);
    }
}

// ============================ bin edges by dst ========================
__global__ void bin_kernel(const float* __restrict__ x,
                           const void* __restrict__ ei_raw,
                           __half* __restrict__ msgh) {
    int e = blockIdx.x * blockDim.x + threadIdx.x;
    if (e >= N_EDGES) return;
    int src, dst;
    if (g_is64) {
        const long long* ei = (const long long*)ei_raw;
        src = (int)ei[e]; dst = (int)ei[N_EDGES + e];
    } else {
        const int* ei = (const int*)ei_raw;
        src = ei[e]; dst = ei[N_EDGES + e];
    }
    if ((unsigned)src >= N_NODES || (unsigned)dst >= N_NODES) return;
    int o = atomicAdd(&g_cnt[dst], 1);
    if (o < CAP) {
        g_bin[dst * CAP + o] = src;
    } else {
        // essentially-never fallback: atomic-add row into fp16 msg (zeroed)
        const float4* xr = (const float4*)(x + (size_t)src * D);
        __half2* mp = (__half2*)(msgh + (size_t)dst * D);
#pragma unroll
        for (int i = 0; i < 32; i++) {
            float4 v = xr[i];
            atomicAdd(mp + i * 2,     __floats2half2_rn(v.x, v.y));
            atomicAdd(mp + i * 2 + 1, __floats2half2_rn(v.z, v.w));
        }
    }
}

// ================= fused gather + fp16 GEMM ===========================
// CTA: 128 nodes. Phase 1: prefetch W/x via cp.async, gather-aggregate agg
// into smem (fp16). Phase 2: 4x K64 MMA chunks. 2 CTAs/SM overlap phases.
__global__ __launch_bounds__(256, 2)
void fused_kernel(const __half* __restrict__ xh,
                  const __half* __restrict__ wth,
                  const float* __restrict__ bias,
                  const __half* __restrict__ msgh,
                  float* __restrict__ out) {
    extern __shared__ char smc[];
    __half* sB0   = (__half*)(smc);
    __half* sB1   = (__half*)(smc + 16384);
    __half* sAx0  = (__half*)(smc + 32768);
    __half* sAx1  = (__half*)(smc + 49152);
    __half* sAgg0 = (__half*)(smc + 65536);
    __half* sAgg1 = (__half*)(smc + 81920);
    float* sBias  = (float*)(smc + 98304);

    const int tid = threadIdx.x;
    const int wid = tid >> 5, lid = tid & 31;
    const int grp = lid >> 2, thr = lid & 3;
    const int wm = (wid & 3) * 32;
    const int wn = (wid >> 2) * 64;
    const int n0 = blockIdx.x * GM;

    const uint32_t b_u[2] = { smem_u32(sB0), smem_u32(sB1) };
    const uint32_t x_u[2] = { smem_u32(sAx0), smem_u32(sAx1) };

    // stage a 64-half K chunk of W (c) into buffer bu
    auto stageB = [&](uint32_t bu, int c) {
#pragma unroll
        for (int i = 0; i < 4; i++) {
            int idx = tid + i * 256;          // 0..1023
            int row = idx >> 3;
            int kk = (idx & 7) * 8;           // half index in chunk
            cpa16(bu + swz(row, kk * 2), wth + row * 256 + c * 64 + kk);
        }
    };
    // stage x chunk cx (0/1) into buffer
    auto stageX = [&](uint32_t xu, int cx) {
#pragma unroll
        for (int i = 0; i < 4; i++) {
            int idx = tid + i * 256;
            int row = idx >> 3;
            int kk = (idx & 7) * 8;
            int g = min(n0 + row, N_NODES - 1);
            cpa16(xu + swz(row, kk * 2), xh + (size_t)g * D + cx * 64 + kk);
        }
    };

    // prefetch x0, x1, B0 (land during gather)  -> group G1
    stageX(x_u[0], 0);
    stageX(x_u[1], 1);
    stageB(b_u[0], 0);
    CP_COMMIT();
    if (tid < 128) sBias[tid] = bias[tid];

    // ---------------- gather phase: warp w -> rows w, w+8, ..., w+120
    for (int j = 0; j < 16; j++) {
        int row = wid + j * 8;
        int g = n0 + row;
        float4 acc = make_float4(0.f, 0.f, 0.f, 0.f);
        float inv = 1.0f;
        if (g < N_NODES) {
            int deg = g_cnt[g];
            int n = min(deg, CAP);
            const int* bp = g_bin + (size_t)g * CAP;
            int i0 = (lid < n) ? bp[lid] : 0;
            int n1 = min(n, 32);
#pragma unroll 4
            for (int i = 0; i < n1; i++) {
                int s = __shfl_sync(0xFFFFFFFFu, i0, i);
                uint2 p = __ldg((const uint2*)(xh + (size_t)s * D) + lid);
                float2 lo = __half22float2(*(const __half2*)&p.x);
                float2 hi = __half22float2(*(const __half2*)&p.y);
                acc.x += lo.x; acc.y += lo.y; acc.z += hi.x; acc.w += hi.y;
            }
            if (n > 32) {
                int i1 = (32 + lid < n) ? bp[32 + lid] : 0;
                for (int i = 32; i < n; i++) {
                    int s = __shfl_sync(0xFFFFFFFFu, i1, i - 32);
                    uint2 p = __ldg((const uint2*)(xh + (size_t)s * D) + lid);
                    float2 lo = __half22float2(*(const __half2*)&p.x);
                    float2 hi = __half22float2(*(const __half2*)&p.y);
                    acc.x += lo.x; acc.y += lo.y; acc.z += hi.x; acc.w += hi.y;
                }
            }
            if (deg > CAP) {              // merge never-path fallback deposits
                uint2 m = __ldg((const uint2*)(msgh + (size_t)g * D) + lid);
                float2 lo = __half22float2(*(const __half2*)&m.x);
                float2 hi = __half22float2(*(const __half2*)&m.y);
                acc.x += lo.x; acc.y += lo.y; acc.z += hi.x; acc.w += hi.y;
            }
            inv = 1.0f / fmaxf((float)deg, 1.0f);
        }
        __half2 h0 = __floats2half2_rn(acc.x * inv, acc.y * inv);
        __half2 h1 = __floats2half2_rn(acc.z * inv, acc.w * inv);
        uint2 st;
        st.x = *(const uint32_t*)&h0;
        st.y = *(const uint32_t*)&h1;
        // lanes 0-15 -> agg chunk 0 (k 0..63), lanes 16-31 -> chunk 1
        __half* dst = (lid < 16) ? sAgg0 : sAgg1;
        *(uint2*)((char*)dst + swz(row, (lid & 15) * 8)) = st;
    }

    // ---------------- MMA phase: 4 chunks of K=64 halves
    float acc[2][8][4];
#pragma unroll
    for (int mt = 0; mt < 2; mt++)
#pragma unroll
        for (int nt = 0; nt < 8; nt++)
#pragma unroll
            for (int i = 0; i < 4; i++) acc[mt][nt][i] = 0.f;

    const __half* Asrc[4] = { sAgg0, sAgg1, sAx0, sAx1 };

    for (int c = 0; c < 4; c++) {
        if (c < 3) { stageB(b_u[(c + 1) & 1], c + 1); CP_COMMIT(); CP_WAIT(1); }
        else       { CP_WAIT(0); }
        __syncthreads();              // staged data + gather stores visible

        const char* A = (const char*)Asrc[c];
        const char* B = (const char*)((c & 1) ? sB1 : sB0);
#pragma unroll
        for (int ks = 0; ks < 4; ks++) {
            const int kb = ks * 32 + thr * 4;     // byte offset in row
            uint32_t a[2][4];
#pragma unroll
            for (int mt = 0; mt < 2; mt++) {
                int r0 = wm + mt * 16 + grp;
                a[mt][0] = *(const uint32_t*)(A + swz(r0, kb));
                a[mt][1] = *(const uint32_t*)(A + swz(r0 + 8, kb));
                a[mt][2] = *(const uint32_t*)(A + swz(r0, kb + 16));
                a[mt][3] = *(const uint32_t*)(A + swz(r0 + 8, kb + 16));
            }
#pragma unroll
            for (int nt = 0; nt < 8; nt++) {
                int n = wn + nt * 8 + grp;
                uint32_t b0 = *(const uint32_t*)(B + swz(n, kb));
                uint32_t b1 = *(const uint32_t*)(B + swz(n, kb + 16));
                mma_f16(acc[0][nt], a[0], b0, b1);
                mma_f16(acc[1][nt], a[1], b0, b1);
            }
        }
        __syncthreads();              // done reading before B-buffer reuse
    }

    // ---------------- epilogue
#pragma unroll
    for (int mt = 0; mt < 2; mt++) {
        int rA = n0 + wm + mt * 16 + grp;
        int rB = rA + 8;
#pragma unroll
        for (int nt = 0; nt < 8; nt++) {
            int c = wn + nt * 8 + thr * 2;
            float b0 = sBias[c], b1 = sBias[c + 1];
            if (rA < N_NODES) {
                float2 r;
                r.x = fmaxf(acc[mt][nt][0] + b0, 0.f);
                r.y = fmaxf(acc[mt][nt][1] + b1, 0.f);
                *(float2*)(out + (size_t)rA * D + c) = r;
            }
            if (rB < N_NODES) {
                float2 r;
                r.x = fmaxf(acc[mt][nt][2] + b0, 0.f);
                r.y = fmaxf(acc[mt][nt][3] + b1, 0.f);
                *(float2*)(out + (size_t)rB * D + c) = r;
            }
        }
    }
}

// ============================ launch =================================
extern "C" void kernel_launch(void* const* d_in, const int* in_sizes, int n_in,
                              void* d_out, int out_size) {
    const float* x  = (const float*)d_in[0];
    const void*  ei = d_in[1];
    const float* Wl = (const float*)d_in[2];
    const float* bl = (const float*)d_in[3];
    const float* Wr = (const float*)d_in[4];
    float* out = (float*)d_out;

    __half *msgh, *wth, *xh; int* cnt;
    cudaGetSymbolAddress((void**)&msgh, g_msgh);
    cudaGetSymbolAddress((void**)&cnt, g_cnt);
    cudaGetSymbolAddress((void**)&wth, g_wth);
    cudaGetSymbolAddress((void**)&xh, g_xh);

    prep_kernel<<<(N_NODES * D / 2 + 255) / 256, 256>>>(
        Wl, Wr, x, (const long long*)ei, (__half2*)wth, cnt, (__half2*)xh);
    cudaMemsetAsync(msgh, 0, sizeof(__half) * (size_t)N_NODES * D);
    bin_kernel<<<(N_EDGES + 255) / 256, 256>>>(x, ei, msgh);

    int smem = 98304 + 512;
    cudaFuncSetAttribute(fused_kernel,
                         cudaFuncAttributeMaxDynamicSharedMemorySize, smem);
    int gblocks = (N_NODES + GM - 1) / GM;
    fused_kernel<<<gblocks, 256, smem>>>(xh, wth, bl, msgh, out);
}

// round 10
// speedup vs baseline: 1.6366x; 1.6366x over previous
#include <cuda_runtime.h>
#include <cuda_fp16.h>
#include <cstdint>

#define N_NODES 100000
#define N_EDGES 1600000
#define D 128
#define CAP 64            // bin capacity per destination
#define GM 128            // nodes per GEMM CTA
#define ASTH 72           // smem tile stride (halves): conflict-free fragment map
#define NCH 4             // K chunks of 64 halves
#define GW 8              // gather warps per block

// ---- scratch (no allocations allowed) ----
__device__ __half g_msgh[N_NODES * D];     // agg, fp16
__device__ int    g_cnt[N_NODES];
__device__ int    g_bin[N_NODES * CAP];
__device__ __half g_wth[128 * 256];        // [Wl|Wr] fp16, [n][k]
__device__ __half g_xh[N_NODES * D];       // fp16 copy of x
__device__ int    g_is64;

__device__ __forceinline__ void mma_f16(float* c, const uint32_t* a,
                                        uint32_t b0, uint32_t b1) {
    asm volatile(
        "mma.sync.aligned.m16n8k16.row.col.f32.f16.f16.f32 "
        "{%0,%1,%2,%3}, {%4,%5,%6,%7}, {%8,%9}, {%0,%1,%2,%3};"
        : "+f"(c[0]), "+f"(c[1]), "+f"(c[2]), "+f"(c[3])
        : "r"(a[0]), "r"(a[1]), "r"(a[2]), "r"(a[3]), "r"(b0), "r"(b1));
}
__device__ __forceinline__ uint32_t smem_u32(const void* p) {
    uint32_t a;
    asm("{ .reg .u64 t; cvta.to.shared.u64 t, %1; cvt.u32.u64 %0, t; }" : "=r"(a) : "l"(p));
    return a;
}
__device__ __forceinline__ void cpa16(uint32_t dst, const void* src) {
    asm volatile("cp.async.cg.shared.global [%0], [%1], 16;" :: "r"(dst), "l"(src));
}
#define CP_COMMIT() asm volatile("cp.async.commit_group;" ::: "memory")
#define CP_WAIT(n)  asm volatile("cp.async.wait_group %0;" :: "n"(n) : "memory")

// ============ prep: dtype detect + W->fp16 + cnt zero + x->fp16 =======
__global__ void prep_kernel(const float* __restrict__ Wl,
                            const float* __restrict__ Wr,
                            const float* __restrict__ x,
                            const long long* __restrict__ ei64,
                            __half2* __restrict__ wth2,
                            int* __restrict__ cnt,
                            uint2* __restrict__ xh4) {
    if (blockIdx.x == 0 && threadIdx.x < 32) {
        int lane = threadIdx.x;
        int bad = 0;
        for (int i = lane; i < 1024; i += 32) {
            long long v = ei64[i];
            if (v < 0 || v >= N_NODES) bad = 1;
        }
        unsigned m = __ballot_sync(0xFFFFFFFFu, bad);
        if (lane == 0) g_is64 = (m == 0u) ? 1 : 0;
    }
    int i = blockIdx.x * 256 + threadIdx.x;
    if (i < 128 * 128) {                 // W as half2 pairs
        int n = i >> 7, k = (i & 127) * 2;
        float a, b;
        if (k < 128) { a = Wl[n * 128 + k];       b = Wl[n * 128 + k + 1]; }
        else         { a = Wr[n * 128 + k - 128]; b = Wr[n * 128 + k - 127]; }
        wth2[i] = __floats2half2_rn(a, b);
    }
    if (i < N_NODES) cnt[i] = 0;
    if (i < N_NODES * D / 4) {           // x -> fp16, 4 elems/thread
        float4 v = ((const float4*)x)[i];
        __half2 h0 = __floats2half2_rn(v.x, v.y);
        __half2 h1 = __floats2half2_rn(v.z, v.w);
        uint2 st;
        st.x = *(const uint32_t*)&h0;
        st.y = *(const uint32_t*)&h1;
        xh4[i] = st;
    }
}

// ============================ bin edges by dst ========================
__global__ void bin_kernel(const float* __restrict__ x,
                           const void* __restrict__ ei_raw,
                           __half* __restrict__ msgh) {
    int e = blockIdx.x * blockDim.x + threadIdx.x;
    if (e >= N_EDGES) return;
    int src, dst;
    if (g_is64) {
        const long long* ei = (const long long*)ei_raw;
        src = (int)ei[e]; dst = (int)ei[N_EDGES + e];
    } else {
        const int* ei = (const int*)ei_raw;
        src = ei[e]; dst = ei[N_EDGES + e];
    }
    if ((unsigned)src >= N_NODES || (unsigned)dst >= N_NODES) return;
    int o = atomicAdd(&g_cnt[dst], 1);
    if (o < CAP) {
        g_bin[dst * CAP + o] = src;
    } else {
        // essentially-never fallback: atomic-add row into fp16 msg (zeroed)
        const float4* xr = (const float4*)(x + (size_t)src * D);
        __half2* mp = (__half2*)(msgh + (size_t)dst * D);
#pragma unroll
        for (int i = 0; i < 32; i++) {
            float4 v = xr[i];
            atomicAdd(mp + i * 2,     __floats2half2_rn(v.x, v.y));
            atomicAdd(mp + i * 2 + 1, __floats2half2_rn(v.z, v.w));
        }
    }
}

// ============================ gather-aggregate ========================
// One warp per dst. Half-warps process 2 edges/iter; lane covers 16 B of the
// 256 B row via LDG.128. Edge indices staged in smem (LDS broadcast).
__global__ void gather_kernel(const __half* __restrict__ xh,
                              __half* __restrict__ msgh) {
    __shared__ int sidx[GW][CAP];
    const int wbl = threadIdx.x >> 5;
    const int lane = threadIdx.x & 31;
    const int w = blockIdx.x * GW + wbl;
    if (w >= N_NODES) return;

    const int deg = g_cnt[w];
    const int n = min(deg, CAP);
    const int* bp = g_bin + (size_t)w * CAP;
    if (lane < n) sidx[wbl][lane] = bp[lane];
    if (32 + lane < n) sidx[wbl][32 + lane] = bp[32 + lane];
    __syncwarp();

    const int hw = lane >> 4;        // half-warp: edge offset
    const int col = lane & 15;       // 16-byte chunk of the row
    float acc[8] = {0.f, 0.f, 0.f, 0.f, 0.f, 0.f, 0.f, 0.f};

#pragma unroll 4
    for (int i = 0; i < n; i += 2) {
        int e = i + hw;
        if (e < n) {
            int s = sidx[wbl][e];
            uint4 p = __ldg((const uint4*)(xh + (size_t)s * D) + col);
            float2 f0 = __half22float2(*(const __half2*)&p.x);
            float2 f1 = __half22float2(*(const __half2*)&p.y);
            float2 f2 = __half22float2(*(const __half2*)&p.z);
            float2 f3 = __half22float2(*(const __half2*)&p.w);
            acc[0] += f0.x; acc[1] += f0.y; acc[2] += f1.x; acc[3] += f1.y;
            acc[4] += f2.x; acc[5] += f2.y; acc[6] += f3.x; acc[7] += f3.y;
        }
    }
    // merge the two half-warps
#pragma unroll
    for (int j = 0; j < 8; j++)
        acc[j] += __shfl_xor_sync(0xFFFFFFFFu, acc[j], 16);

    if (hw == 0) {
        if (deg > CAP) {             // merge never-path fallback deposits
            uint4 m = __ldg((const uint4*)(msgh + (size_t)w * D) + col);
            float2 f0 = __half22float2(*(const __half2*)&m.x);
            float2 f1 = __half22float2(*(const __half2*)&m.y);
            float2 f2 = __half22float2(*(const __half2*)&m.z);
            float2 f3 = __half22float2(*(const __half2*)&m.w);
            acc[0] += f0.x; acc[1] += f0.y; acc[2] += f1.x; acc[3] += f1.y;
            acc[4] += f2.x; acc[5] += f2.y; acc[6] += f3.x; acc[7] += f3.y;
        }
        float inv = 1.0f / fmaxf((float)deg, 1.0f);
        __half2 h0 = __floats2half2_rn(acc[0] * inv, acc[1] * inv);
        __half2 h1 = __floats2half2_rn(acc[2] * inv, acc[3] * inv);
        __half2 h2 = __floats2half2_rn(acc[4] * inv, acc[5] * inv);
        __half2 h3 = __floats2half2_rn(acc[6] * inv, acc[7] * inv);
        uint4 st;
        st.x = *(const uint32_t*)&h0;
        st.y = *(const uint32_t*)&h1;
        st.z = *(const uint32_t*)&h2;
        st.w = *(const uint32_t*)&h3;
        ((uint4*)(msgh + (size_t)w * D))[col] = st;
    }
}

// ===================== fp16 mma GEMM, cp.async pipelined ==============
// out = relu( [agg | x] @ wt^T + b ); fp16 inputs, fp32 accumulate.
// K = 4 chunks of 64, double-buffered, 2 CTAs/SM.  (unchanged from R8)
__global__ __launch_bounds__(256, 2)
void gemm_kernel(const __half* __restrict__ xh,
                 const __half* __restrict__ wth,
                 const float* __restrict__ bias,
                 const __half* __restrict__ msgh,
                 float* __restrict__ out) {
    extern __shared__ char smc[];
    __half* sB0 = (__half*)smc;
    __half* sB1 = sB0 + 128 * ASTH;
    __half* sA0 = sB1 + 128 * ASTH;
    __half* sA1 = sA0 + 128 * ASTH;
    float* sBias = (float*)(smc + 4 * 128 * ASTH * 2);

    const int tid = threadIdx.x;
    const int wid = tid >> 5, lid = tid & 31;
    const int grp = lid >> 2, thr = lid & 3;
    const int wm = (wid & 3) * 32;
    const int wn = (wid >> 2) * 64;
    const int n0 = blockIdx.x * GM;

    const uint32_t sb_u[2] = { smem_u32(sB0), smem_u32(sB1) };
    const uint32_t sa_u[2] = { smem_u32(sA0), smem_u32(sA1) };
    const __half* const sBp[2] = { sB0, sB1 };
    const __half* const sAp[2] = { sA0, sA1 };

    if (tid < 128) sBias[tid] = bias[tid];

    auto stage = [&](int b, int c) {
#pragma unroll
        for (int i = 0; i < 4; i++) {
            int idx = tid + i * 256;
            int row = idx >> 3;
            int kk = (idx & 7) * 8;
            uint32_t so = (uint32_t)(row * ASTH + kk) * 2u;
            cpa16(sb_u[b] + so, wth + row * 256 + c * 64 + kk);
            int g = min(n0 + row, N_NODES - 1);
            const __half* ap = (c < 2)
                ? msgh + (size_t)g * D + c * 64 + kk
                : xh + (size_t)g * D + (c - 2) * 64 + kk;
            cpa16(sa_u[b] + so, ap);
        }
    };

    float acc[2][8][4];
#pragma unroll
    for (int mt = 0; mt < 2; mt++)
#pragma unroll
        for (int nt = 0; nt < 8; nt++)
#pragma unroll
            for (int i = 0; i < 4; i++) acc[mt][nt][i] = 0.f;

    stage(0, 0); CP_COMMIT();

    for (int c = 0; c < NCH; c++) {
        if (c < NCH - 1) { stage((c + 1) & 1, c + 1); CP_COMMIT(); CP_WAIT(1); }
        else             { CP_WAIT(0); }
        __syncthreads();

        const __half* A = sAp[c & 1];
        const __half* B = sBp[c & 1];
#pragma unroll
        for (int ks = 0; ks < 4; ks++) {
            const int k0 = ks * 16;
            uint32_t a[2][4];
#pragma unroll
            for (int mt = 0; mt < 2; mt++) {
                int r0 = wm + mt * 16 + grp;
                a[mt][0] = *(const uint32_t*)(A + r0 * ASTH + k0 + thr * 2);
                a[mt][1] = *(const uint32_t*)(A + (r0 + 8) * ASTH + k0 + thr * 2);
                a[mt][2] = *(const uint32_t*)(A + r0 * ASTH + k0 + 8 + thr * 2);
                a[mt][3] = *(const uint32_t*)(A + (r0 + 8) * ASTH + k0 + 8 + thr * 2);
            }
#pragma unroll
            for (int nt = 0; nt < 8; nt++) {
                int n = wn + nt * 8 + grp;
                uint32_t b0 = *(const uint32_t*)(B + n * ASTH + k0 + thr * 2);
                uint32_t b1 = *(const uint32_t*)(B + n * ASTH + k0 + 8 + thr * 2);
                mma_f16(acc[0][nt], a[0], b0, b1);
                mma_f16(acc[1][nt], a[1], b0, b1);
            }
        }
        __syncthreads();
    }

#pragma unroll
    for (int mt = 0; mt < 2; mt++) {
        int rA = n0 + wm + mt * 16 + grp;
        int rB = rA + 8;
#pragma unroll
        for (int nt = 0; nt < 8; nt++) {
            int c = wn + nt * 8 + thr * 2;
            float b0 = sBias[c], b1 = sBias[c + 1];
            if (rA < N_NODES) {
                float2 r;
                r.x = fmaxf(acc[mt][nt][0] + b0, 0.f);
                r.y = fmaxf(acc[mt][nt][1] + b1, 0.f);
                *(float2*)(out + (size_t)rA * D + c) = r;
            }
            if (rB < N_NODES) {
                float2 r;
                r.x = fmaxf(acc[mt][nt][2] + b0, 0.f);
                r.y = fmaxf(acc[mt][nt][3] + b1, 0.f);
                *(float2*)(out + (size_t)rB * D + c) = r;
            }
        }
    }
}

// ============================ launch =================================
extern "C" void kernel_launch(void* const* d_in, const int* in_sizes, int n_in,
                              void* d_out, int out_size) {
    const float* x  = (const float*)d_in[0];
    const void*  ei = d_in[1];
    const float* Wl = (const float*)d_in[2];
    const float* bl = (const float*)d_in[3];
    const float* Wr = (const float*)d_in[4];
    float* out = (float*)d_out;

    __half *msgh, *wth, *xh; int* cnt;
    cudaGetSymbolAddress((void**)&msgh, g_msgh);
    cudaGetSymbolAddress((void**)&cnt, g_cnt);
    cudaGetSymbolAddress((void**)&wth, g_wth);
    cudaGetSymbolAddress((void**)&xh, g_xh);

    prep_kernel<<<(N_NODES * D / 4 + 255) / 256, 256>>>(
        Wl, Wr, x, (const long long*)ei, (__half2*)wth, cnt, (uint2*)xh);
    cudaMemsetAsync(msgh, 0, sizeof(__half) * (size_t)N_NODES * D);
    bin_kernel<<<(N_EDGES + 255) / 256, 256>>>(x, ei, msgh);
    gather_kernel<<<(N_NODES + GW - 1) / GW, GW * 32>>>(xh, msgh);

    int smem = 4 * 128 * ASTH * 2 + 128 * 4;   // 74240 B
    cudaFuncSetAttribute(gemm_kernel,
                         cudaFuncAttributeMaxDynamicSharedMemorySize, smem);
    int gblocks = (N_NODES + GM - 1) / GM;
    gemm_kernel<<<gblocks, 256, smem>>>(xh, wth, bl, msgh, out);
}

// round 12
// speedup vs baseline: 1.8074x; 1.1043x over previous
#include <cuda_runtime.h>
#include <cuda_fp16.h>
#include <cstdint>

#define N_NODES 100000
#define N_EDGES 1600000
#define D 128
#define CAP 64            // bin capacity per destination
#define GM 128            // nodes per GEMM CTA

// XOR-swizzled byte offset in a 128-row x 128-byte chunk buffer
#define SWZ(row, kb) ((row) * 128 + ((kb) ^ (((row) & 7) << 4)))

// ---- scratch (no allocations allowed) ----
__device__ __half g_msgh[N_NODES * D];     // agg, fp16
__device__ int    g_cnt[N_NODES];
__device__ int    g_bin[N_NODES * CAP];
__device__ __half g_wth[128 * 256];        // [Wl|Wr] fp16, [n][k]
__device__ __half g_xh[N_NODES * D];       // fp16 copy of x
__device__ int    g_is64;

__device__ __forceinline__ void mma_f16(float* c, const uint32_t* a,
                                        uint32_t b0, uint32_t b1) {
    asm volatile(
        "mma.sync.aligned.m16n8k16.row.col.f32.f16.f16.f32 "
        "{%0,%1,%2,%3}, {%4,%5,%6,%7}, {%8,%9}, {%0,%1,%2,%3};"
        : "+f"(c[0]), "+f"(c[1]), "+f"(c[2]), "+f"(c[3])
        : "r"(a[0]), "r"(a[1]), "r"(a[2]), "r"(a[3]), "r"(b0), "r"(b1));
}
__device__ __forceinline__ void ldsm4(uint32_t* r, uint32_t addr) {
    asm volatile("ldmatrix.sync.aligned.m8n8.x4.shared.b16 {%0,%1,%2,%3}, [%4];"
                 : "=r"(r[0]), "=r"(r[1]), "=r"(r[2]), "=r"(r[3]) : "r"(addr));
}
__device__ __forceinline__ uint32_t smem_u32(const void* p) {
    uint32_t a;
    asm("{ .reg .u64 t; cvta.to.shared.u64 t, %1; cvt.u32.u64 %0, t; }" : "=r"(a) : "l"(p));
    return a;
}
__device__ __forceinline__ void cpa16(uint32_t dst, const void* src) {
    asm volatile("cp.async.cg.shared.global [%0], [%1], 16;" :: "r"(dst), "l"(src));
}
#define CP_COMMIT() asm volatile("cp.async.commit_group;" ::: "memory")
#define CP_WAIT(n)  asm volatile("cp.async.wait_group %0;" :: "n"(n) : "memory")

// ============ prep: dtype detect + W->fp16 + cnt zero + x->fp16 =======
__global__ void prep_kernel(const float* __restrict__ Wl,
                            const float* __restrict__ Wr,
                            const float* __restrict__ x,
                            const long long* __restrict__ ei64,
                            __half2* __restrict__ wth2,
                            int* __restrict__ cnt,
                            uint2* __restrict__ xh4) {
    if (blockIdx.x == 0 && threadIdx.x < 32) {
        int lane = threadIdx.x;
        int bad = 0;
        for (int i = lane; i < 1024; i += 32) {
            long long v = ei64[i];
            if (v < 0 || v >= N_NODES) bad = 1;
        }
        unsigned m = __ballot_sync(0xFFFFFFFFu, bad);
        if (lane == 0) g_is64 = (m == 0u) ? 1 : 0;
    }
    int i = blockIdx.x * 256 + threadIdx.x;
    if (i < 128 * 128) {
        int n = i >> 7, k = (i & 127) * 2;
        float a, b;
        if (k < 128) { a = Wl[n * 128 + k];       b = Wl[n * 128 + k + 1]; }
        else         { a = Wr[n * 128 + k - 128]; b = Wr[n * 128 + k - 127]; }
        wth2[i] = __floats2half2_rn(a, b);
    }
    if (i < N_NODES) cnt[i] = 0;
    if (i < N_NODES * D / 4) {
        float4 v = ((const float4*)x)[i];
        __half2 h0 = __floats2half2_rn(v.x, v.y);
        __half2 h1 = __floats2half2_rn(v.z, v.w);
        uint2 st;
        st.x = *(const uint32_t*)&h0;
        st.y = *(const uint32_t*)&h1;
        xh4[i] = st;
    }
}

// ============================ bin edges by dst ========================
// 4 edges per thread (grid-stride) -> 4 independent atomics in flight.
__global__ void bin_kernel(const float* __restrict__ x,
                           const void* __restrict__ ei_raw,
                           __half* __restrict__ msgh) {
    int base = blockIdx.x * blockDim.x + threadIdx.x;
    int stride = gridDim.x * blockDim.x;
#pragma unroll
    for (int q = 0; q < 4; q++) {
        int e = base + q * stride;
        if (e >= N_EDGES) break;
        int src, dst;
        if (g_is64) {
            const long long* ei = (const long long*)ei_raw;
            src = (int)ei[e]; dst = (int)ei[N_EDGES + e];
        } else {
            const int* ei = (const int*)ei_raw;
            src = ei[e]; dst = ei[N_EDGES + e];
        }
        if ((unsigned)src >= N_NODES || (unsigned)dst >= N_NODES) continue;
        int o = atomicAdd(&g_cnt[dst], 1);
        if (o < CAP) {
            g_bin[dst * CAP + o] = src;
        } else {
            // essentially-never fallback: atomic-add row into fp16 msg (zeroed)
            const float4* xr = (const float4*)(x + (size_t)src * D);
            __half2* mp = (__half2*)(msgh + (size_t)dst * D);
#pragma unroll
            for (int i = 0; i < 32; i++) {
                float4 v = xr[i];
                atomicAdd(mp + i * 2,     __floats2half2_rn(v.x, v.y));
                atomicAdd(mp + i * 2 + 1, __floats2half2_rn(v.z, v.w));
            }
        }
    }
}

// ============================ gather-aggregate ========================
// Half-warp per destination node (100000 = 16 * 6250, exact). Lane covers a
// 16 B chunk of the 256 B row via LDG.128; indices broadcast from smem.
__global__ void gather_kernel(const __half* __restrict__ xh,
                              __half* __restrict__ msgh) {
    __shared__ int sidx[16][CAP];
    const int hw = threadIdx.x >> 4;          // half-warp 0..15
    const int l = threadIdx.x & 15;
    const int w = blockIdx.x * 16 + hw;       // exact: grid = 6250

    const int deg = g_cnt[w];
    const int n = min(deg, CAP);
    const int* bp = g_bin + (size_t)w * CAP;
    for (int j = l; j < n; j += 16) sidx[hw][j] = bp[j];
    __syncwarp();

    float acc[8] = {0.f, 0.f, 0.f, 0.f, 0.f, 0.f, 0.f, 0.f};
#pragma unroll 4
    for (int i = 0; i < n; i++) {
        int s = sidx[hw][i];
        uint4 p = __ldg((const uint4*)(xh + (size_t)s * D) + l);
        float2 f0 = __half22float2(*(const __half2*)&p.x);
        float2 f1 = __half22float2(*(const __half2*)&p.y);
        float2 f2 = __half22float2(*(const __half2*)&p.z);
        float2 f3 = __half22float2(*(const __half2*)&p.w);
        acc[0] += f0.x; acc[1] += f0.y; acc[2] += f1.x; acc[3] += f1.y;
        acc[4] += f2.x; acc[5] += f2.y; acc[6] += f3.x; acc[7] += f3.y;
    }

    if (deg > CAP) {             // merge never-path fallback deposits
        uint4 m = __ldg((const uint4*)(msgh + (size_t)w * D) + l);
        float2 f0 = __half22float2(*(const __half2*)&m.x);
        float2 f1 = __half22float2(*(const __half2*)&m.y);
        float2 f2 = __half22float2(*(const __half2*)&m.z);
        float2 f3 = __half22float2(*(const __half2*)&m.w);
        acc[0] += f0.x; acc[1] += f0.y; acc[2] += f1.x; acc[3] += f1.y;
        acc[4] += f2.x; acc[5] += f2.y; acc[6] += f3.x; acc[7] += f3.y;
    }
    float inv = 1.0f / fmaxf((float)deg, 1.0f);
    __half2 h0 = __floats2half2_rn(acc[0] * inv, acc[1] * inv);
    __half2 h1 = __floats2half2_rn(acc[2] * inv, acc[3] * inv);
    __half2 h2 = __floats2half2_rn(acc[4] * inv, acc[5] * inv);
    __half2 h3 = __floats2half2_rn(acc[6] * inv, acc[7] * inv);
    uint4 st;
    st.x = *(const uint32_t*)&h0;
    st.y = *(const uint32_t*)&h1;
    st.z = *(const uint32_t*)&h2;
    st.w = *(const uint32_t*)&h3;
    ((uint4*)(msgh + (size_t)w * D))[l] = st;
}

// ============ fp16 mma GEMM: ldmatrix + XOR swizzle + cp.async ========
// out = relu( [agg | x] @ wt^T + b ); K = 4 chunks of 64 halves (128 B rows).
// A and B are both [row][k] layouts -> NON-trans ldmatrix for both.
__global__ __launch_bounds__(256, 2)
void gemm_kernel(const __half* __restrict__ xh,
                 const __half* __restrict__ wth,
                 const float* __restrict__ bias,
                 const __half* __restrict__ msgh,
                 float* __restrict__ out) {
    extern __shared__ char smc[];
    float* sBias = (float*)(smc + 65536);

    const int tid = threadIdx.x;
    const int wid = tid >> 5, lid = tid & 31;
    const int grp = lid >> 2, thr = lid & 3;
    const int wm = (wid & 3) * 32;
    const int wn = (wid >> 2) * 64;
    const int n0 = blockIdx.x * GM;

    const uint32_t sb = smem_u32(smc);
    const uint32_t ub[2] = { sb,          sb + 16384 };   // B chunk buffers
    const uint32_t ua[2] = { sb + 32768,  sb + 49152 };   // A chunk buffers

    if (tid < 128) sBias[tid] = bias[tid];

    // stage chunk c (64 halves = 128 B per row) into buffer b
    auto stage = [&](int b, int c) {
#pragma unroll
        for (int i = 0; i < 4; i++) {
            int idx = tid + i * 256;          // 0..1023
            int row = idx >> 3;
            int kb = (idx & 7) * 16;          // byte in 128B row
            cpa16(ub[b] + SWZ(row, kb), wth + row * 256 + c * 64 + kb / 2);
            int g = min(n0 + row, N_NODES - 1);
            const __half* ap = (c < 2)
                ? msgh + (size_t)g * D + c * 64 + kb / 2
                : xh + (size_t)g * D + (c - 2) * 64 + kb / 2;
            cpa16(ua[b] + SWZ(row, kb), ap);
        }
    };

    // per-lane ldmatrix address components (x4 over a 16-row x 16-k-byte... 
    // 32-byte tile pair): lanes 0-15 -> rows 0-15 col-byte 0, lanes 16-31 ->
    // rows 0-15 col-byte 16. Output: m0=(r0-7,k0-7) m1=(r8-15,k0-7)
    // m2=(r0-7,k8-15) m3=(r8-15,k8-15).
    const int rowf = lid & 15;
    const int colf = (lid >> 4) * 16;

    float acc[2][8][4];
#pragma unroll
    for (int mt = 0; mt < 2; mt++)
#pragma unroll
        for (int nt = 0; nt < 8; nt++)
#pragma unroll
            for (int i = 0; i < 4; i++) acc[mt][nt][i] = 0.f;

    stage(0, 0); CP_COMMIT();

    for (int c = 0; c < 4; c++) {
        if (c < 3) { stage((c + 1) & 1, c + 1); CP_COMMIT(); CP_WAIT(1); }
        else       { CP_WAIT(0); }
        __syncthreads();

        const uint32_t A = ua[c & 1];
        const uint32_t B = ub[c & 1];
#pragma unroll
        for (int ks = 0; ks < 4; ks++) {
            const int kbase = ks * 32;        // bytes
            // A fragments: af[mt] = {m0,m1,m2,m3} == a0..a3 directly
            uint32_t af[2][4];
#pragma unroll
            for (int mt = 0; mt < 2; mt++) {
                int r = wm + mt * 16 + rowf;
                ldsm4(af[mt], A + SWZ(r, kbase + colf));
            }
            // B fragments: x4 over 16 n-rows; bf[2p]={m0,m2}, bf[2p+1]={m1,m3}
            uint32_t bf[8][2];
#pragma unroll
            for (int p = 0; p < 4; p++) {
                uint32_t t[4];
                int r = wn + p * 16 + rowf;
                ldsm4(t, B + SWZ(r, kbase + colf));
                bf[2 * p][0] = t[0]; bf[2 * p][1] = t[2];
                bf[2 * p + 1][0] = t[1]; bf[2 * p + 1][1] = t[3];
            }
#pragma unroll
            for (int nt = 0; nt < 8; nt++) {
                mma_f16(acc[0][nt], af[0], bf[nt][0], bf[nt][1]);
                mma_f16(acc[1][nt], af[1], bf[nt][0], bf[nt][1]);
            }
        }
        __syncthreads();
    }

    // epilogue: c0/c1 at (row grp, col 2thr), c2/c3 at row grp+8
#pragma unroll
    for (int mt = 0; mt < 2; mt++) {
        int rA = n0 + wm + mt * 16 + grp;
        int rB = rA + 8;
#pragma unroll
        for (int nt = 0; nt < 8; nt++) {
            int c = wn + nt * 8 + thr * 2;
            float b0 = sBias[c], b1 = sBias[c + 1];
            if (rA < N_NODES) {
                float2 r;
                r.x = fmaxf(acc[mt][nt][0] + b0, 0.f);
                r.y = fmaxf(acc[mt][nt][1] + b1, 0.f);
                *(float2*)(out + (size_t)rA * D + c) = r;
            }
            if (rB < N_NODES) {
                float2 r;
                r.x = fmaxf(acc[mt][nt][2] + b0, 0.f);
                r.y = fmaxf(acc[mt][nt][3] + b1, 0.f);
                *(float2*)(out + (size_t)rB * D + c) = r;
            }
        }
    }
}

// ============================ launch =================================
extern "C" void kernel_launch(void* const* d_in, const int* in_sizes, int n_in,
                              void* d_out, int out_size) {
    const float* x  = (const float*)d_in[0];
    const void*  ei = d_in[1];
    const float* Wl = (const float*)d_in[2];
    const float* bl = (const float*)d_in[3];
    const float* Wr = (const float*)d_in[4];
    float* out = (float*)d_out;

    __half *msgh, *wth, *xh; int* cnt;
    cudaGetSymbolAddress((void**)&msgh, g_msgh);
    cudaGetSymbolAddress((void**)&cnt, g_cnt);
    cudaGetSymbolAddress((void**)&wth, g_wth);
    cudaGetSymbolAddress((void**)&xh, g_xh);

    prep_kernel<<<(N_NODES * D / 4 + 255) / 256, 256>>>(
        Wl, Wr, x, (const long long*)ei, (__half2*)wth, cnt, (uint2*)xh);
    cudaMemsetAsync(msgh, 0, sizeof(__half) * (size_t)N_NODES * D);
    bin_kernel<<<(N_EDGES + 1023) / 1024, 256>>>(x, ei, msgh);
    gather_kernel<<<N_NODES / 16, 256>>>(xh, msgh);

    int smem = 65536 + 512;
    cudaFuncSetAttribute(gemm_kernel,
                         cudaFuncAttributeMaxDynamicSharedMemorySize, smem);
    int gblocks = (N_NODES + GM - 1) / GM;
    gemm_kernel<<<gblocks, 256, smem>>>(xh, wth, bl, msgh, out);
}